// round 13
// baseline (speedup 1.0000x reference)
#include <cuda_runtime.h>

// Problem shape (fixed by dataset)
#define BB 8
#define DD 8
#define PP (512 * 1024)
#define PV (PP / 4)                  // 131072 float4/int4 quads per image
#define KK 5

#define TPB 256
#define P1CH 37                      // pass1: 37*8*2 = 592 blocks (4/SM x 148)
#define P1TH (P1CH * TPB)            // 9472 threads per (b,z) group
#define P2CH 74                      // pass2: 74*8 = 592 blocks
#define P2TH (P2CH * TPB)            // 18944 threads per image
#define NBLK2 (P2CH * BB)            // 592

#define DELTA_V 0.5f
#define DELTA_D 3.0f
#define GAMMA_W 0.001f

// Scratch (no allocations allowed -> __device__ globals).
// Zero-initialized at module load; re-zeroed by the finalize step at the end
// of every run so each graph replay starts clean.
__device__ float g_sums[BB * KK * DD];     // 320 floats
__device__ float g_counts[BB * KK];        // 40
__device__ float g_var[BB];                // 8
__device__ unsigned int g_done;

__device__ __forceinline__ float warp_sum(float v) {
    #pragma unroll
    for (int o = 16; o > 0; o >>= 1) v += __shfl_down_sync(0xffffffffu, v, o);
    return v;
}

// ---------------------------------------------------------------------------
// Pass 1: segment sums + counts. d-split via blockIdx.z (4 planes each) to
// keep accumulators at 20 -> <=64 regs -> 4 blocks/SM.
// grid (37, 8, 2), block 256.
// ---------------------------------------------------------------------------
__global__ void __launch_bounds__(TPB, 4) k_pass1(const float4* __restrict__ emb,
                                                  const int4* __restrict__ mask) {
    const int b = blockIdx.y;
    const int z = blockIdx.z;                    // planes [4z, 4z+4)
    const float4* __restrict__ eb = emb + ((size_t)b * DD + (size_t)z * 4) * PV;
    const int4* __restrict__ mb = mask + (size_t)b * PV;

    float s[KK * 4];
    float cnt[KK];
    #pragma unroll
    for (int i = 0; i < KK * 4; i++) s[i] = 0.f;
    #pragma unroll
    for (int k = 0; k < KK; k++) cnt[k] = 0.f;

    for (int i = blockIdx.x * TPB + threadIdx.x; i < PV; i += P1TH) {
        int4 mm = mb[i];
        float w0[KK], w1[KK], w2[KK], w3[KK];
        #pragma unroll
        for (int k = 0; k < KK; k++) {
            w0[k] = (mm.x == k + 1) ? 1.f : 0.f;
            w1[k] = (mm.y == k + 1) ? 1.f : 0.f;
            w2[k] = (mm.z == k + 1) ? 1.f : 0.f;
            w3[k] = (mm.w == k + 1) ? 1.f : 0.f;
            cnt[k] += (w0[k] + w1[k]) + (w2[k] + w3[k]);
        }
        #pragma unroll
        for (int d = 0; d < 4; ++d) {
            float4 ev = eb[(size_t)d * PV + i];
            #pragma unroll
            for (int k = 0; k < KK; k++) {
                float a = s[k * 4 + d];
                a = fmaf(ev.x, w0[k], a);
                a = fmaf(ev.y, w1[k], a);
                a = fmaf(ev.z, w2[k], a);
                a = fmaf(ev.w, w3[k], a);
                s[k * 4 + d] = a;
            }
        }
    }

    // Block reduction: 20 sums + 5 counts
    __shared__ float red[8][28];
    const int warp = threadIdx.x >> 5, lane = threadIdx.x & 31;
    #pragma unroll
    for (int v = 0; v < KK * 4; v++) {
        float r = warp_sum(s[v]);
        if (lane == 0) red[warp][v] = r;
    }
    #pragma unroll
    for (int k = 0; k < KK; k++) {
        float r = warp_sum(cnt[k]);
        if (lane == 0) red[warp][KK * 4 + k] = r;
    }
    __syncthreads();
    const int t = threadIdx.x;
    if (t < KK * 4) {
        float acc = 0.f;
        #pragma unroll
        for (int w = 0; w < 8; w++) acc += red[w][t];
        atomicAdd(&g_sums[b * KK * DD + (t >> 2) * DD + z * 4 + (t & 3)], acc);
    } else if (t < KK * 4 + KK && z == 0) {
        float acc = 0.f;
        #pragma unroll
        for (int w = 0; w < 8; w++) acc += red[w][t];
        atomicAdd(&g_counts[b * KK + (t - KK * 4)], acc);
    }
}

// ---------------------------------------------------------------------------
// Pass 2: per-pixel variance term; LAST block also runs the finalize epilogue
// (pairwise dist + reg + batch means) and resets scratch for the next replay.
// grid (74, 8), block 256.
// ---------------------------------------------------------------------------
__global__ void __launch_bounds__(TPB, 4) k_pass2(const float4* __restrict__ emb,
                                                  const int4* __restrict__ mask,
                                                  float* __restrict__ out,
                                                  int out_size) {
    __shared__ __align__(16) float cs[48];   // [0,40) centers k*8+d, [40,45) inv
    const int b = blockIdx.y;
    {
        const int t = threadIdx.x;
        if (t < 40) {
            float c = g_counts[b * KK + (t >> 3)];
            cs[t] = g_sums[b * KK * DD + t] * (1.f / fmaxf(c, 1.f));
        } else if (t < 45) {
            float c = g_counts[b * KK + (t - 40)];
            cs[t] = (c > 0.f) ? (1.f / c) : 0.f;
        }
    }
    __syncthreads();
    const float4* cs4 = (const float4*)cs;

    const float4* __restrict__ eb = emb + (size_t)b * DD * PV;
    const int4* __restrict__ mb = mask + (size_t)b * PV;

    float acc = 0.f;
    for (int i = blockIdx.x * TPB + threadIdx.x; i < PV; i += P2TH) {
        int4 mm = mb[i];
        const int k0 = min(max(mm.x - 1, 0), KK - 1) * 2;   // float4 index
        const int k1 = min(max(mm.y - 1, 0), KK - 1) * 2;
        const int k2 = min(max(mm.z - 1, 0), KK - 1) * 2;
        const int k3 = min(max(mm.w - 1, 0), KK - 1) * 2;

        float c0[4], c1[4], c2[4], c3[4];
        *(float4*)c0 = cs4[k0];
        *(float4*)c1 = cs4[k1];
        *(float4*)c2 = cs4[k2];
        *(float4*)c3 = cs4[k3];

        float a0 = 0.f, a1 = 0.f, a2 = 0.f, a3 = 0.f;
        #pragma unroll
        for (int d = 0; d < 4; ++d) {
            float4 ev = eb[(size_t)d * PV + i];
            float t0 = ev.x - c0[d]; a0 = fmaf(t0, t0, a0);
            float t1 = ev.y - c1[d]; a1 = fmaf(t1, t1, a1);
            float t2 = ev.z - c2[d]; a2 = fmaf(t2, t2, a2);
            float t3 = ev.w - c3[d]; a3 = fmaf(t3, t3, a3);
        }
        *(float4*)c0 = cs4[k0 + 1];
        *(float4*)c1 = cs4[k1 + 1];
        *(float4*)c2 = cs4[k2 + 1];
        *(float4*)c3 = cs4[k3 + 1];
        #pragma unroll
        for (int d = 4; d < 8; ++d) {
            float4 ev = eb[(size_t)d * PV + i];
            float t0 = ev.x - c0[d - 4]; a0 = fmaf(t0, t0, a0);
            float t1 = ev.y - c1[d - 4]; a1 = fmaf(t1, t1, a1);
            float t2 = ev.z - c2[d - 4]; a2 = fmaf(t2, t2, a2);
            float t3 = ev.w - c3[d - 4]; a3 = fmaf(t3, t3, a3);
        }

        float w0 = (mm.x > 0) ? cs[40 + (k0 >> 1)] : 0.f;
        float w1 = (mm.y > 0) ? cs[40 + (k1 >> 1)] : 0.f;
        float w2 = (mm.z > 0) ? cs[40 + (k2 >> 1)] : 0.f;
        float w3 = (mm.w > 0) ? cs[40 + (k3 >> 1)] : 0.f;

        float v0 = fmaxf(sqrtf(a0) - DELTA_V, 0.f);
        float v1 = fmaxf(sqrtf(a1) - DELTA_V, 0.f);
        float v2 = fmaxf(sqrtf(a2) - DELTA_V, 0.f);
        float v3 = fmaxf(sqrtf(a3) - DELTA_V, 0.f);
        acc += fmaf(v0 * v0, w0, v1 * v1 * w1) + fmaf(v2 * v2, w2, v3 * v3 * w3);
    }

    __shared__ float red[8];
    const int warp = threadIdx.x >> 5, lane = threadIdx.x & 31;
    float r = warp_sum(acc);
    if (lane == 0) red[warp] = r;
    __syncthreads();
    if (threadIdx.x == 0) {
        float s = 0.f;
        #pragma unroll
        for (int w = 0; w < 8; w++) s += red[w];
        atomicAdd(&g_var[b], s);
    }

    // ---------------- last-block finalize + scratch reset -----------------
    __shared__ bool is_last;
    if (threadIdx.x == 0) {
        __threadfence();
        unsigned t = atomicAdd(&g_done, 1u);
        is_last = (t == NBLK2 - 1);
    }
    __syncthreads();
    if (!is_last) return;

    __shared__ float pr[BB][4];
    const int tid = threadIdx.x;
    if (tid < BB) {
        const int bb = tid;
        float cnt[KK], pres[KK];
        float N = 0.f;
        #pragma unroll
        for (int k = 0; k < KK; k++) {
            cnt[k] = g_counts[bb * KK + k];
            pres[k] = (cnt[k] > 0.f) ? 1.f : 0.f;
            N += pres[k];
        }
        float c[KK][DD];
        #pragma unroll
        for (int k = 0; k < KK; k++) {
            float inv = 1.f / fmaxf(cnt[k], 1.f);
            #pragma unroll
            for (int d = 0; d < DD; d++)
                c[k][d] = g_sums[bb * KK * DD + k * DD + d] * inv;
        }
        float dist = 0.f;
        #pragma unroll
        for (int i = 0; i < KK; i++) {
            #pragma unroll
            for (int j = i + 1; j < KK; j++) {
                if (pres[i] > 0.f && pres[j] > 0.f) {
                    float dsq = 0.f;
                    #pragma unroll
                    for (int d = 0; d < DD; d++) {
                        float df = c[i][d] - c[j][d];
                        dsq = fmaf(df, df, dsq);
                    }
                    float term = fmaxf(2.f * DELTA_D - sqrtf(dsq), 0.f);
                    dist += term * term;
                }
            }
        }
        float npairs = N * (N - 1.f) * 0.5f;
        float reg = 0.f;
        #pragma unroll
        for (int k = 0; k < KK; k++) {
            if (pres[k] > 0.f) {
                float nsq = 0.f;
                #pragma unroll
                for (int d = 0; d < DD; d++) nsq = fmaf(c[k][d], c[k][d], nsq);
                reg += sqrtf(nsq);
            }
        }
        pr[bb][0] = __ldcg(&g_var[bb]) / fmaxf(N, 1.f);     // var_b (L2-fresh)
        pr[bb][1] = dist / ((N > 1.f) ? npairs : 1.f);       // dist_b
        pr[bb][2] = reg / fmaxf(N, 1.f);                     // reg_b
        pr[bb][3] = (N > 0.f) ? 1.f : 0.f;                   // has
    }
    __syncthreads();

    if (tid == 0) {
        float sv = 0.f, sd = 0.f, sr = 0.f, hs = 0.f;
        #pragma unroll
        for (int bb = 0; bb < BB; bb++) {
            sv += pr[bb][0] * pr[bb][3];
            sd += pr[bb][1] * pr[bb][3];
            sr += pr[bb][2] * pr[bb][3];
            hs += pr[bb][3];
        }
        float den = fmaxf(hs, 1.f);
        sv /= den; sd /= den; sr /= den;
        float total = sv + sd + GAMMA_W * sr;
        float res[4] = {total, sv, sd, sr};
        for (int i = 0; i < 4 && i < out_size; i++) out[i] = res[i];
    }

    // Reset ALL scratch for the next graph replay (strided: 320 > TPB!)
    for (int i = tid; i < BB * KK * DD; i += TPB) g_sums[i] = 0.f;
    for (int i = tid; i < BB * KK; i += TPB) g_counts[i] = 0.f;
    for (int i = tid; i < BB; i += TPB) g_var[i] = 0.f;
    __syncthreads();
    if (tid == 0) { __threadfence(); g_done = 0u; }
}

// ---------------------------------------------------------------------------
extern "C" void kernel_launch(void* const* d_in, const int* in_sizes, int n_in,
                              void* d_out, int out_size) {
    const float4* emb = (const float4*)d_in[0];
    const int4* mask = (const int4*)d_in[1];

    dim3 g1(P1CH, BB, 2);
    k_pass1<<<g1, TPB>>>(emb, mask);
    dim3 g2(P2CH, BB);
    k_pass2<<<g2, TPB>>>(emb, mask, (float*)d_out, out_size);
}

// round 14
// speedup vs baseline: 1.0354x; 1.0354x over previous
#include <cuda_runtime.h>

// Problem shape (fixed by dataset)
#define BB 8
#define DD 8
#define PP (512 * 1024)
#define PV (PP / 4)                  // 131072 float4/int4 quads per image
#define KK 5

#define TPB 256
#define P1CH 37                      // pass1: 37*8*2 = 592 blocks (4/SM x 148)
#define P1TH (P1CH * TPB)            // 9472 threads per (b,z) group
#define P2CH 74                      // pass2: 74*8 = 592 blocks
#define P2TH (P2CH * TPB)            // 18944 threads per image
#define NBLK2 (P2CH * BB)            // 592

#define DELTA_V 0.5f
#define DELTA_D 3.0f
#define GAMMA_W 0.001f

// Scratch (no allocations allowed -> __device__ globals).
// g_sums/g_counts/g_var/g_done are accumulated -> reset at end of each run.
// g_distb/g_regb/g_Nb are overwritten unconditionally each run (no reset needed).
__device__ float g_sums[BB * KK * DD];     // 320 floats
__device__ float g_counts[BB * KK];        // 40
__device__ float g_var[BB];                // 8
__device__ float g_distb[BB];
__device__ float g_regb[BB];
__device__ float g_Nb[BB];
__device__ unsigned int g_done;

__device__ __forceinline__ float warp_sum(float v) {
    #pragma unroll
    for (int o = 16; o > 0; o >>= 1) v += __shfl_down_sync(0xffffffffu, v, o);
    return v;
}

// ---------------------------------------------------------------------------
// Pass 1: segment sums + counts. d-split via blockIdx.z (4 planes each) to
// keep accumulators at 20 -> <=64 regs -> 4 blocks/SM.
// grid (37, 8, 2), block 256.
// ---------------------------------------------------------------------------
__global__ void __launch_bounds__(TPB, 4) k_pass1(const float4* __restrict__ emb,
                                                  const int4* __restrict__ mask) {
    const int b = blockIdx.y;
    const int z = blockIdx.z;                    // planes [4z, 4z+4)
    const float4* __restrict__ eb = emb + ((size_t)b * DD + (size_t)z * 4) * PV;
    const int4* __restrict__ mb = mask + (size_t)b * PV;

    float s[KK * 4];
    float cnt[KK];
    #pragma unroll
    for (int i = 0; i < KK * 4; i++) s[i] = 0.f;
    #pragma unroll
    for (int k = 0; k < KK; k++) cnt[k] = 0.f;

    for (int i = blockIdx.x * TPB + threadIdx.x; i < PV; i += P1TH) {
        int4 mm = mb[i];
        float w0[KK], w1[KK], w2[KK], w3[KK];
        #pragma unroll
        for (int k = 0; k < KK; k++) {
            w0[k] = (mm.x == k + 1) ? 1.f : 0.f;
            w1[k] = (mm.y == k + 1) ? 1.f : 0.f;
            w2[k] = (mm.z == k + 1) ? 1.f : 0.f;
            w3[k] = (mm.w == k + 1) ? 1.f : 0.f;
            cnt[k] += (w0[k] + w1[k]) + (w2[k] + w3[k]);
        }
        #pragma unroll
        for (int d = 0; d < 4; ++d) {
            float4 ev = eb[(size_t)d * PV + i];
            #pragma unroll
            for (int k = 0; k < KK; k++) {
                float a = s[k * 4 + d];
                a = fmaf(ev.x, w0[k], a);
                a = fmaf(ev.y, w1[k], a);
                a = fmaf(ev.z, w2[k], a);
                a = fmaf(ev.w, w3[k], a);
                s[k * 4 + d] = a;
            }
        }
    }

    // Block reduction: 20 sums + 5 counts
    __shared__ float red[8][28];
    const int warp = threadIdx.x >> 5, lane = threadIdx.x & 31;
    #pragma unroll
    for (int v = 0; v < KK * 4; v++) {
        float r = warp_sum(s[v]);
        if (lane == 0) red[warp][v] = r;
    }
    #pragma unroll
    for (int k = 0; k < KK; k++) {
        float r = warp_sum(cnt[k]);
        if (lane == 0) red[warp][KK * 4 + k] = r;
    }
    __syncthreads();
    const int t = threadIdx.x;
    if (t < KK * 4) {
        float acc = 0.f;
        #pragma unroll
        for (int w = 0; w < 8; w++) acc += red[w][t];
        atomicAdd(&g_sums[b * KK * DD + (t >> 2) * DD + z * 4 + (t & 3)], acc);
    } else if (t < KK * 4 + KK && z == 0) {
        float acc = 0.f;
        #pragma unroll
        for (int w = 0; w < 8; w++) acc += red[w][t];
        atomicAdd(&g_counts[b * KK + (t - KK * 4)], acc);
    }
}

// ---------------------------------------------------------------------------
// Pass 2: per-pixel variance term. blockIdx.x==0 blocks also compute
// dist_b/reg_b/N_b from the staged centers (overlapped with everyone else's
// mainloop). Last block (ticket) does a tiny combine + scratch reset.
// grid (74, 8), block 256.
// ---------------------------------------------------------------------------
__global__ void __launch_bounds__(TPB, 4) k_pass2(const float4* __restrict__ emb,
                                                  const int4* __restrict__ mask,
                                                  float* __restrict__ out,
                                                  int out_size) {
    __shared__ __align__(16) float cs[48];   // [0,40) centers k*8+d, [40,45) inv
    const int b = blockIdx.y;
    {
        const int t = threadIdx.x;
        if (t < 40) {
            float c = g_counts[b * KK + (t >> 3)];
            cs[t] = g_sums[b * KK * DD + t] * (1.f / fmaxf(c, 1.f));
        } else if (t < 45) {
            float c = g_counts[b * KK + (t - 40)];
            cs[t] = (c > 0.f) ? (1.f / c) : 0.f;
        }
    }
    __syncthreads();

    // -------- overlapped per-image center math (one block per image) ------
    if (blockIdx.x == 0) {
        __shared__ float aux[16];
        const int t = threadIdx.x;
        if (t < 10) {
            // pair (i,j), i<j, from triangular index (cold path)
            const int pi[10] = {0, 0, 0, 0, 1, 1, 1, 2, 2, 3};
            const int pj[10] = {1, 2, 3, 4, 2, 3, 4, 3, 4, 4};
            const int i = pi[t], j = pj[t];
            float dsq = 0.f;
            #pragma unroll
            for (int d = 0; d < DD; d++) {
                float df = cs[i * DD + d] - cs[j * DD + d];
                dsq = fmaf(df, df, dsq);
            }
            float term = 0.f;
            if (cs[40 + i] > 0.f && cs[40 + j] > 0.f) {
                float h = fmaxf(2.f * DELTA_D - sqrtf(dsq), 0.f);
                term = h * h;
            }
            aux[t] = term;
        } else if (t < 15) {
            const int k = t - 10;
            float nsq = 0.f;
            #pragma unroll
            for (int d = 0; d < DD; d++)
                nsq = fmaf(cs[k * DD + d], cs[k * DD + d], nsq);
            aux[t] = (cs[40 + k] > 0.f) ? sqrtf(nsq) : 0.f;
        } else if (t == 15) {
            float N = 0.f;
            #pragma unroll
            for (int k = 0; k < KK; k++) N += (cs[40 + k] > 0.f) ? 1.f : 0.f;
            aux[15] = N;
        }
        __syncthreads();
        if (t == 0) {
            float N = aux[15];
            float dist = 0.f, reg = 0.f;
            #pragma unroll
            for (int p = 0; p < 10; p++) dist += aux[p];
            #pragma unroll
            for (int k = 0; k < KK; k++) reg += aux[10 + k];
            float npairs = N * (N - 1.f) * 0.5f;
            g_distb[b] = dist / ((N > 1.f) ? npairs : 1.f);
            g_regb[b] = reg / fmaxf(N, 1.f);
            g_Nb[b] = N;
        }
    }

    // ------------------------------ mainloop ------------------------------
    const float4* cs4 = (const float4*)cs;
    const float4* __restrict__ eb = emb + (size_t)b * DD * PV;
    const int4* __restrict__ mb = mask + (size_t)b * PV;

    float acc = 0.f;
    for (int i = blockIdx.x * TPB + threadIdx.x; i < PV; i += P2TH) {
        int4 mm = mb[i];
        const int k0 = min(max(mm.x - 1, 0), KK - 1) * 2;   // float4 index
        const int k1 = min(max(mm.y - 1, 0), KK - 1) * 2;
        const int k2 = min(max(mm.z - 1, 0), KK - 1) * 2;
        const int k3 = min(max(mm.w - 1, 0), KK - 1) * 2;

        float c0[4], c1[4], c2[4], c3[4];
        *(float4*)c0 = cs4[k0];
        *(float4*)c1 = cs4[k1];
        *(float4*)c2 = cs4[k2];
        *(float4*)c3 = cs4[k3];

        float a0 = 0.f, a1 = 0.f, a2 = 0.f, a3 = 0.f;
        #pragma unroll
        for (int d = 0; d < 4; ++d) {
            float4 ev = eb[(size_t)d * PV + i];
            float t0 = ev.x - c0[d]; a0 = fmaf(t0, t0, a0);
            float t1 = ev.y - c1[d]; a1 = fmaf(t1, t1, a1);
            float t2 = ev.z - c2[d]; a2 = fmaf(t2, t2, a2);
            float t3 = ev.w - c3[d]; a3 = fmaf(t3, t3, a3);
        }
        *(float4*)c0 = cs4[k0 + 1];
        *(float4*)c1 = cs4[k1 + 1];
        *(float4*)c2 = cs4[k2 + 1];
        *(float4*)c3 = cs4[k3 + 1];
        #pragma unroll
        for (int d = 4; d < 8; ++d) {
            float4 ev = eb[(size_t)d * PV + i];
            float t0 = ev.x - c0[d - 4]; a0 = fmaf(t0, t0, a0);
            float t1 = ev.y - c1[d - 4]; a1 = fmaf(t1, t1, a1);
            float t2 = ev.z - c2[d - 4]; a2 = fmaf(t2, t2, a2);
            float t3 = ev.w - c3[d - 4]; a3 = fmaf(t3, t3, a3);
        }

        float w0 = (mm.x > 0) ? cs[40 + (k0 >> 1)] : 0.f;
        float w1 = (mm.y > 0) ? cs[40 + (k1 >> 1)] : 0.f;
        float w2 = (mm.z > 0) ? cs[40 + (k2 >> 1)] : 0.f;
        float w3 = (mm.w > 0) ? cs[40 + (k3 >> 1)] : 0.f;

        float v0 = fmaxf(sqrtf(a0) - DELTA_V, 0.f);
        float v1 = fmaxf(sqrtf(a1) - DELTA_V, 0.f);
        float v2 = fmaxf(sqrtf(a2) - DELTA_V, 0.f);
        float v3 = fmaxf(sqrtf(a3) - DELTA_V, 0.f);
        acc += fmaf(v0 * v0, w0, v1 * v1 * w1) + fmaf(v2 * v2, w2, v3 * v3 * w3);
    }

    __shared__ float red[8];
    const int warp = threadIdx.x >> 5, lane = threadIdx.x & 31;
    float r = warp_sum(acc);
    if (lane == 0) red[warp] = r;
    __syncthreads();
    if (threadIdx.x == 0) {
        float s = 0.f;
        #pragma unroll
        for (int w = 0; w < 8; w++) s += red[w];
        atomicAdd(&g_var[b], s);
    }

    // ------------- last-block tiny combine + scratch reset ----------------
    __shared__ bool is_last;
    if (threadIdx.x == 0) {
        __threadfence();
        unsigned t = atomicAdd(&g_done, 1u);
        is_last = (t == NBLK2 - 1);
    }
    __syncthreads();
    if (!is_last) return;

    const int tid = threadIdx.x;
    if (tid < 32) {
        float sv = 0.f, sd = 0.f, sr = 0.f, hs = 0.f;
        if (tid < BB) {
            float N = __ldcg(&g_Nb[tid]);
            float has = (N > 0.f) ? 1.f : 0.f;
            sv = (__ldcg(&g_var[tid]) / fmaxf(N, 1.f)) * has;
            sd = __ldcg(&g_distb[tid]) * has;
            sr = __ldcg(&g_regb[tid]) * has;
            hs = has;
        }
        // reduce over the 8 active lanes (others contribute 0)
        #pragma unroll
        for (int o = 4; o > 0; o >>= 1) {
            sv += __shfl_down_sync(0xffffffffu, sv, o);
            sd += __shfl_down_sync(0xffffffffu, sd, o);
            sr += __shfl_down_sync(0xffffffffu, sr, o);
            hs += __shfl_down_sync(0xffffffffu, hs, o);
        }
        if (tid == 0) {
            float den = fmaxf(hs, 1.f);
            sv /= den; sd /= den; sr /= den;
            float total = sv + sd + GAMMA_W * sr;
            float res[4] = {total, sv, sd, sr};
            for (int i = 0; i < 4 && i < out_size; i++) out[i] = res[i];
        }
    }

    // Reset accumulated scratch for next graph replay (strided: 320 > TPB)
    for (int i = tid; i < BB * KK * DD; i += TPB) g_sums[i] = 0.f;
    for (int i = tid; i < BB * KK; i += TPB) g_counts[i] = 0.f;
    for (int i = tid; i < BB; i += TPB) g_var[i] = 0.f;
    __syncthreads();
    if (tid == 0) { __threadfence(); g_done = 0u; }
}

// ---------------------------------------------------------------------------
extern "C" void kernel_launch(void* const* d_in, const int* in_sizes, int n_in,
                              void* d_out, int out_size) {
    const float4* emb = (const float4*)d_in[0];
    const int4* mask = (const int4*)d_in[1];

    dim3 g1(P1CH, BB, 2);
    k_pass1<<<g1, TPB>>>(emb, mask);
    dim3 g2(P2CH, BB);
    k_pass2<<<g2, TPB>>>(emb, mask, (float*)d_out, out_size);
}

// round 15
// speedup vs baseline: 1.1062x; 1.0684x over previous
#include <cuda_runtime.h>

// Problem shape (fixed by dataset)
#define BB 8
#define DD 8
#define PP (512 * 1024)
#define PV (PP / 4)                  // 131072 float4/int4 quads per image
#define KK 5
#define HB 4                         // images per half-batch (72 MB -> fits L2)

#define TPB 256
#define P1CH 74                      // pass1 half: 74*4*2 = 592 blocks
#define P1TH (P1CH * TPB)            // 18944 threads per (b,z) group
#define P2CH 148                     // pass2 half: 148*4 = 592 blocks
#define P2TH (P2CH * TPB)            // 37888 threads per image
#define NBLK2 (P2CH * HB)            // 592 (ticket for the final launch only)

#define DELTA_V 0.5f
#define DELTA_D 3.0f
#define GAMMA_W 0.001f

// Scratch (no allocations allowed -> __device__ globals).
// g_sums/g_counts/g_var/g_done accumulate -> reset by the final block each run.
// g_distb/g_regb/g_Nb overwritten unconditionally each run.
__device__ float g_sums[BB * KK * DD];     // 320
__device__ float g_counts[BB * KK];        // 40
__device__ float g_var[BB];                // 8
__device__ float g_distb[BB];
__device__ float g_regb[BB];
__device__ float g_Nb[BB];
__device__ unsigned int g_done;

__device__ __forceinline__ float warp_sum(float v) {
    #pragma unroll
    for (int o = 16; o > 0; o >>= 1) v += __shfl_down_sync(0xffffffffu, v, o);
    return v;
}

// ---------------------------------------------------------------------------
// Pass 1 (half-batch): segment sums + counts for images [b0, b0+4).
// d-split via blockIdx.z (4 planes each) keeps accumulators at 20 -> 4 blk/SM.
// grid (74, 4, 2), block 256.
// ---------------------------------------------------------------------------
__global__ void __launch_bounds__(TPB, 4) k_pass1(const float4* __restrict__ emb,
                                                  const int4* __restrict__ mask,
                                                  int b0) {
    const int b = b0 + blockIdx.y;
    const int z = blockIdx.z;                    // planes [4z, 4z+4)
    const float4* __restrict__ eb = emb + ((size_t)b * DD + (size_t)z * 4) * PV;
    const int4* __restrict__ mb = mask + (size_t)b * PV;

    float s[KK * 4];
    float cnt[KK];
    #pragma unroll
    for (int i = 0; i < KK * 4; i++) s[i] = 0.f;
    #pragma unroll
    for (int k = 0; k < KK; k++) cnt[k] = 0.f;

    for (int i = blockIdx.x * TPB + threadIdx.x; i < PV; i += P1TH) {
        int4 mm = mb[i];
        float w0[KK], w1[KK], w2[KK], w3[KK];
        #pragma unroll
        for (int k = 0; k < KK; k++) {
            w0[k] = (mm.x == k + 1) ? 1.f : 0.f;
            w1[k] = (mm.y == k + 1) ? 1.f : 0.f;
            w2[k] = (mm.z == k + 1) ? 1.f : 0.f;
            w3[k] = (mm.w == k + 1) ? 1.f : 0.f;
            cnt[k] += (w0[k] + w1[k]) + (w2[k] + w3[k]);
        }
        #pragma unroll
        for (int d = 0; d < 4; ++d) {
            float4 ev = eb[(size_t)d * PV + i];
            #pragma unroll
            for (int k = 0; k < KK; k++) {
                float a = s[k * 4 + d];
                a = fmaf(ev.x, w0[k], a);
                a = fmaf(ev.y, w1[k], a);
                a = fmaf(ev.z, w2[k], a);
                a = fmaf(ev.w, w3[k], a);
                s[k * 4 + d] = a;
            }
        }
    }

    // Block reduction: 20 sums + 5 counts
    __shared__ float red[8][28];
    const int warp = threadIdx.x >> 5, lane = threadIdx.x & 31;
    #pragma unroll
    for (int v = 0; v < KK * 4; v++) {
        float r = warp_sum(s[v]);
        if (lane == 0) red[warp][v] = r;
    }
    #pragma unroll
    for (int k = 0; k < KK; k++) {
        float r = warp_sum(cnt[k]);
        if (lane == 0) red[warp][KK * 4 + k] = r;
    }
    __syncthreads();
    const int t = threadIdx.x;
    if (t < KK * 4) {
        float acc = 0.f;
        #pragma unroll
        for (int w = 0; w < 8; w++) acc += red[w][t];
        atomicAdd(&g_sums[b * KK * DD + (t >> 2) * DD + z * 4 + (t & 3)], acc);
    } else if (t < KK * 4 + KK && z == 0) {
        float acc = 0.f;
        #pragma unroll
        for (int w = 0; w < 8; w++) acc += red[w][t];
        atomicAdd(&g_counts[b * KK + (t - KK * 4)], acc);
    }
}

// ---------------------------------------------------------------------------
// Pass 2 (half-batch): per-pixel variance term for images [b0, b0+4), reading
// the half-batch that pass1 just left L2-resident. blockIdx.x==0 blocks also
// compute dist_b/reg_b/N_b (overlapped). If do_final, the last block (ticket)
// combines all 8 images and resets scratch. grid (148, 4), block 256.
// ---------------------------------------------------------------------------
__global__ void __launch_bounds__(TPB, 4) k_pass2(const float4* __restrict__ emb,
                                                  const int4* __restrict__ mask,
                                                  float* __restrict__ out,
                                                  int out_size, int b0,
                                                  int do_final) {
    __shared__ __align__(16) float cs[48];   // [0,40) centers k*8+d, [40,45) inv
    const int b = b0 + blockIdx.y;
    {
        const int t = threadIdx.x;
        if (t < 40) {
            float c = g_counts[b * KK + (t >> 3)];
            cs[t] = g_sums[b * KK * DD + t] * (1.f / fmaxf(c, 1.f));
        } else if (t < 45) {
            float c = g_counts[b * KK + (t - 40)];
            cs[t] = (c > 0.f) ? (1.f / c) : 0.f;
        }
    }
    __syncthreads();

    // -------- overlapped per-image center math (one block per image) ------
    if (blockIdx.x == 0) {
        __shared__ float aux[16];
        const int t = threadIdx.x;
        if (t < 10) {
            const int pi[10] = {0, 0, 0, 0, 1, 1, 1, 2, 2, 3};
            const int pj[10] = {1, 2, 3, 4, 2, 3, 4, 3, 4, 4};
            const int i = pi[t], j = pj[t];
            float dsq = 0.f;
            #pragma unroll
            for (int d = 0; d < DD; d++) {
                float df = cs[i * DD + d] - cs[j * DD + d];
                dsq = fmaf(df, df, dsq);
            }
            float term = 0.f;
            if (cs[40 + i] > 0.f && cs[40 + j] > 0.f) {
                float h = fmaxf(2.f * DELTA_D - sqrtf(dsq), 0.f);
                term = h * h;
            }
            aux[t] = term;
        } else if (t < 15) {
            const int k = t - 10;
            float nsq = 0.f;
            #pragma unroll
            for (int d = 0; d < DD; d++)
                nsq = fmaf(cs[k * DD + d], cs[k * DD + d], nsq);
            aux[t] = (cs[40 + k] > 0.f) ? sqrtf(nsq) : 0.f;
        } else if (t == 15) {
            float N = 0.f;
            #pragma unroll
            for (int k = 0; k < KK; k++) N += (cs[40 + k] > 0.f) ? 1.f : 0.f;
            aux[15] = N;
        }
        __syncthreads();
        if (t == 0) {
            float N = aux[15];
            float dist = 0.f, reg = 0.f;
            #pragma unroll
            for (int p = 0; p < 10; p++) dist += aux[p];
            #pragma unroll
            for (int k = 0; k < KK; k++) reg += aux[10 + k];
            float npairs = N * (N - 1.f) * 0.5f;
            g_distb[b] = dist / ((N > 1.f) ? npairs : 1.f);
            g_regb[b] = reg / fmaxf(N, 1.f);
            g_Nb[b] = N;
        }
    }

    // ------------------------------ mainloop ------------------------------
    const float4* cs4 = (const float4*)cs;
    const float4* __restrict__ eb = emb + (size_t)b * DD * PV;
    const int4* __restrict__ mb = mask + (size_t)b * PV;

    float acc = 0.f;
    for (int i = blockIdx.x * TPB + threadIdx.x; i < PV; i += P2TH) {
        int4 mm = mb[i];
        const int k0 = min(max(mm.x - 1, 0), KK - 1) * 2;   // float4 index
        const int k1 = min(max(mm.y - 1, 0), KK - 1) * 2;
        const int k2 = min(max(mm.z - 1, 0), KK - 1) * 2;
        const int k3 = min(max(mm.w - 1, 0), KK - 1) * 2;

        float c0[4], c1[4], c2[4], c3[4];
        *(float4*)c0 = cs4[k0];
        *(float4*)c1 = cs4[k1];
        *(float4*)c2 = cs4[k2];
        *(float4*)c3 = cs4[k3];

        float a0 = 0.f, a1 = 0.f, a2 = 0.f, a3 = 0.f;
        #pragma unroll
        for (int d = 0; d < 4; ++d) {
            float4 ev = eb[(size_t)d * PV + i];
            float t0 = ev.x - c0[d]; a0 = fmaf(t0, t0, a0);
            float t1 = ev.y - c1[d]; a1 = fmaf(t1, t1, a1);
            float t2 = ev.z - c2[d]; a2 = fmaf(t2, t2, a2);
            float t3 = ev.w - c3[d]; a3 = fmaf(t3, t3, a3);
        }
        *(float4*)c0 = cs4[k0 + 1];
        *(float4*)c1 = cs4[k1 + 1];
        *(float4*)c2 = cs4[k2 + 1];
        *(float4*)c3 = cs4[k3 + 1];
        #pragma unroll
        for (int d = 4; d < 8; ++d) {
            float4 ev = eb[(size_t)d * PV + i];
            float t0 = ev.x - c0[d - 4]; a0 = fmaf(t0, t0, a0);
            float t1 = ev.y - c1[d - 4]; a1 = fmaf(t1, t1, a1);
            float t2 = ev.z - c2[d - 4]; a2 = fmaf(t2, t2, a2);
            float t3 = ev.w - c3[d - 4]; a3 = fmaf(t3, t3, a3);
        }

        float w0 = (mm.x > 0) ? cs[40 + (k0 >> 1)] : 0.f;
        float w1 = (mm.y > 0) ? cs[40 + (k1 >> 1)] : 0.f;
        float w2 = (mm.z > 0) ? cs[40 + (k2 >> 1)] : 0.f;
        float w3 = (mm.w > 0) ? cs[40 + (k3 >> 1)] : 0.f;

        float v0 = fmaxf(sqrtf(a0) - DELTA_V, 0.f);
        float v1 = fmaxf(sqrtf(a1) - DELTA_V, 0.f);
        float v2 = fmaxf(sqrtf(a2) - DELTA_V, 0.f);
        float v3 = fmaxf(sqrtf(a3) - DELTA_V, 0.f);
        acc += fmaf(v0 * v0, w0, v1 * v1 * w1) + fmaf(v2 * v2, w2, v3 * v3 * w3);
    }

    __shared__ float red[8];
    const int warp = threadIdx.x >> 5, lane = threadIdx.x & 31;
    float r = warp_sum(acc);
    if (lane == 0) red[warp] = r;
    __syncthreads();
    if (threadIdx.x == 0) {
        float s = 0.f;
        #pragma unroll
        for (int w = 0; w < 8; w++) s += red[w];
        atomicAdd(&g_var[b], s);
    }

    if (!do_final) return;

    // ------------- last-block tiny combine + scratch reset ----------------
    __shared__ bool is_last;
    if (threadIdx.x == 0) {
        __threadfence();
        unsigned t = atomicAdd(&g_done, 1u);
        is_last = (t == NBLK2 - 1);
    }
    __syncthreads();
    if (!is_last) return;

    const int tid = threadIdx.x;
    if (tid < 32) {
        float sv = 0.f, sd = 0.f, sr = 0.f, hs = 0.f;
        if (tid < BB) {
            float N = __ldcg(&g_Nb[tid]);
            float has = (N > 0.f) ? 1.f : 0.f;
            sv = (__ldcg(&g_var[tid]) / fmaxf(N, 1.f)) * has;
            sd = __ldcg(&g_distb[tid]) * has;
            sr = __ldcg(&g_regb[tid]) * has;
            hs = has;
        }
        #pragma unroll
        for (int o = 4; o > 0; o >>= 1) {
            sv += __shfl_down_sync(0xffffffffu, sv, o);
            sd += __shfl_down_sync(0xffffffffu, sd, o);
            sr += __shfl_down_sync(0xffffffffu, sr, o);
            hs += __shfl_down_sync(0xffffffffu, hs, o);
        }
        if (tid == 0) {
            float den = fmaxf(hs, 1.f);
            sv /= den; sd /= den; sr /= den;
            float total = sv + sd + GAMMA_W * sr;
            float res[4] = {total, sv, sd, sr};
            for (int i = 0; i < 4 && i < out_size; i++) out[i] = res[i];
        }
    }

    // Reset accumulated scratch for next graph replay (strided: 320 > TPB)
    for (int i = tid; i < BB * KK * DD; i += TPB) g_sums[i] = 0.f;
    for (int i = tid; i < BB * KK; i += TPB) g_counts[i] = 0.f;
    for (int i = tid; i < BB; i += TPB) g_var[i] = 0.f;
    __syncthreads();
    if (tid == 0) { __threadfence(); g_done = 0u; }
}

// ---------------------------------------------------------------------------
extern "C" void kernel_launch(void* const* d_in, const int* in_sizes, int n_in,
                              void* d_out, int out_size) {
    const float4* emb = (const float4*)d_in[0];
    const int4* mask = (const int4*)d_in[1];
    float* out = (float*)d_out;

    dim3 g1(P1CH, HB, 2);
    dim3 g2(P2CH, HB);
    // Half-batch 0..3: pass1 streams it from DRAM, pass2 re-reads it from L2.
    k_pass1<<<g1, TPB>>>(emb, mask, 0);
    k_pass2<<<g2, TPB>>>(emb, mask, out, out_size, 0, 0);
    // Half-batch 4..7.
    k_pass1<<<g1, TPB>>>(emb, mask, 4);
    k_pass2<<<g2, TPB>>>(emb, mask, out, out_size, 4, 1);
}